// round 15
// baseline (speedup 1.0000x reference)
#include <cuda_runtime.h>
#include <cuda_fp16.h>
#include <math.h>
#include <stdint.h>

#define Nn    50000
#define NnPad 50176
#define Ee    800000
#define ETn   3
#define Ln    3
#define Hn    4
#define DHn   64
#define NHn   256
#define NCn   16
#define SA    40          // smem row stride in halves (32 data + 8 pad)

// ---------------- scratch (device globals) -----------------------------------
__device__ __align__(16) float g_h[Nn * NHn];
__device__ __align__(16) __half g_z[Nn * ETn * NHn];   // z in fp16 (77 MB, L2-resident)
__device__ __align__(16) float g_el[ETn * Nn * Hn];
__device__ __align__(16) float g_er[ETn * Nn * Hn];
__device__ int g_deg[ETn * Nn];
__device__ int g_cur[ETn * Nn];
__device__ int g_off[ETn * (Nn + 1)];
__device__ __align__(16) unsigned short g_csr_src[ETn * Ee];   // u16 node ids (< 65536)

// single fp16 A and W operands
__device__ __align__(16) __half g_Ah[NnPad * NHn];
__device__ __align__(16) __half g_WT[Ln * ETn * NHn * NHn];   // [l][t][n][k]

// ---------------- helpers ------------------------------------------------------
__device__ __forceinline__ float lrelu(float v) { return v > 0.f ? v : 0.2f * v; }

__device__ __forceinline__ uint32_t smem_u32(const void* p) {
    uint32_t a;
    asm("{ .reg .u64 t; cvta.to.shared.u64 t, %1; cvt.u32.u64 %0, t; }" : "=r"(a) : "l"(p));
    return a;
}
__device__ __forceinline__ void cp16(uint32_t dst, const void* src) {
    asm volatile("cp.async.cg.shared.global [%0], [%1], 16;" :: "r"(dst), "l"(src) : "memory");
}
__device__ __forceinline__ void ldsm4(uint32_t* r, uint32_t addr) {
    asm volatile("ldmatrix.sync.aligned.m8n8.x4.shared.b16 {%0,%1,%2,%3}, [%4];"
                 : "=r"(r[0]), "=r"(r[1]), "=r"(r[2]), "=r"(r[3]) : "r"(addr));
}
__device__ __forceinline__ void mma16816(float* c, const uint32_t* a, uint32_t b0, uint32_t b1) {
    asm volatile(
        "mma.sync.aligned.m16n8k16.row.col.f32.f16.f16.f32 "
        "{%0,%1,%2,%3}, {%4,%5,%6,%7}, {%8,%9}, {%0,%1,%2,%3};"
        : "+f"(c[0]), "+f"(c[1]), "+f"(c[2]), "+f"(c[3])
        : "r"(a[0]), "r"(a[1]), "r"(a[2]), "r"(a[3]), "r"(b0), "r"(b1));
}
// accumulate 8 fp16 z values (one uint4) scaled by alpha
__device__ __forceinline__ void acc8(float* a, uint4 q, float alpha) {
    __half2 h0 = *(__half2*)&q.x, h1 = *(__half2*)&q.y;
    __half2 h2 = *(__half2*)&q.z, h3 = *(__half2*)&q.w;
    float2 f0 = __half22float2(h0), f1 = __half22float2(h1);
    float2 f2 = __half22float2(h2), f3 = __half22float2(h3);
    a[0] = fmaf(alpha, f0.x, a[0]); a[1] = fmaf(alpha, f0.y, a[1]);
    a[2] = fmaf(alpha, f1.x, a[2]); a[3] = fmaf(alpha, f1.y, a[3]);
    a[4] = fmaf(alpha, f2.x, a[4]); a[5] = fmaf(alpha, f2.y, a[5]);
    a[6] = fmaf(alpha, f3.x, a[6]); a[7] = fmaf(alpha, f3.y, a[7]);
}
// extract this lane's head alpha from two packed half2 (3-shfl broadcast scheme)
__device__ __forceinline__ float pick_alpha(uint32_t q01, uint32_t q23, int myh) {
    uint32_t qq = (myh & 2) ? q23 : q01;
    __half2 hh = *(__half2*)&qq;
    return (myh & 1) ? __high2float(hh) : __low2float(hh);
}

// ---------------- CSR hist + prep (independent work, one launch) ---------------
#define NW (Ln * ETn * NHn * NHn)
#define NAq (Nn * (NHn / 4))
__global__ void hist_prep_kernel(const int* __restrict__ dst,
                                 const float* __restrict__ W,
                                 const float* __restrict__ X) {
    int i = blockIdx.x * blockDim.x + threadIdx.x;
    if (i < ETn * Ee) {
        int t = i / Ee;
        atomicAdd(&g_deg[t * Nn + dst[i]], 1);
    }
    if (i < NW) {
        int lt = i / (NHn * NHn);
        int rem = i - lt * NHn * NHn;
        int k = rem / NHn;
        int n = rem - k * NHn;
        size_t o = (size_t)lt * NHn * NHn + (size_t)n * NHn + k;
        g_WT[o] = __float2half(W[i]);
    } else if (i < NW + NAq) {
        int i2 = i - NW;
        float4 v = *(const float4*)(X + (size_t)i2 * 4);
        __half2 a = __floats2half2_rn(v.x, v.y);
        __half2 b = __floats2half2_rn(v.z, v.w);
        *(uint2*)((uint16_t*)g_Ah + (size_t)i2 * 4) =
            make_uint2(*(uint32_t*)&a, *(uint32_t*)&b);
    }
}
__global__ void scan_kernel() {
    int t = blockIdx.x;
    int tid = threadIdx.x;
    __shared__ int warpsums[32];
    __shared__ int s_carry;
    if (tid == 0) s_carry = 0;
    __syncthreads();
    for (int base = 0; base < Nn; base += 1024) {
        int i = base + tid;
        int v = (i < Nn) ? g_deg[t * Nn + i] : 0;
        int x = v;
        #pragma unroll
        for (int o = 1; o < 32; o <<= 1) {
            int y = __shfl_up_sync(0xffffffffu, x, o);
            if ((tid & 31) >= o) x += y;
        }
        if ((tid & 31) == 31) warpsums[tid >> 5] = x;
        __syncthreads();
        if (tid < 32) {
            int w = warpsums[tid];
            #pragma unroll
            for (int o = 1; o < 32; o <<= 1) {
                int y = __shfl_up_sync(0xffffffffu, w, o);
                if (tid >= o) w += y;
            }
            warpsums[tid] = w;
        }
        __syncthreads();
        int add = (tid >= 32) ? warpsums[(tid >> 5) - 1] : 0;
        int incl = x + add;
        int c = s_carry;
        if (i < Nn) g_off[t * (Nn + 1) + i] = c + incl - v;
        __syncthreads();
        if (tid == 1023) s_carry = c + incl;
        __syncthreads();
    }
    if (tid == 0) g_off[t * (Nn + 1) + Nn] = s_carry;
}
__global__ void scatter_kernel(const int* __restrict__ src, const int* __restrict__ dst) {
    int i = blockIdx.x * blockDim.x + threadIdx.x;
    if (i >= ETn * Ee) return;
    int t = i / Ee;
    int d = dst[i];
    int p = atomicAdd(&g_cur[t * Nn + d], 1);
    g_csr_src[t * Ee + g_off[t * (Nn + 1) + d] + p] = (unsigned short)src[i];
}

// ---------------- HMMA GEMM (single fp16 A, 3-stage pipeline) ------------------
__global__ __launch_bounds__(256, 2) void gemm_hmma_kernel(
        int l, const float* __restrict__ AL, const float* __restrict__ AR) {
    extern __shared__ char dyn[];
    __shared__ float s_al[2][DHn];
    __shared__ float s_ar[2][DHn];

    int tid  = threadIdx.x;
    int wid  = tid >> 5;
    int lane = tid & 31;
    int rowBase = blockIdx.x * 128;
    int t    = blockIdx.y >> 1;
    int nOff = (blockIdx.y & 1) * 128;

    const __half* Bw = g_WT + ((size_t)l * ETn + t) * NHn * NHn + (size_t)nOff * NHn;

    uint32_t sbase = smem_u32(dyn);

    if (tid < 128) {
        int w = tid >> 6, i = tid & 63;
        int hg = (nOff >> 6) + w;
        s_al[w][i] = AL[(((size_t)l * ETn + t) * Hn + hg) * DHn + i];
        s_ar[w][i] = AR[(((size_t)l * ETn + t) * Hn + hg) * DHn + i];
    }

    float acc[2][8][4];
    #pragma unroll
    for (int i = 0; i < 2; i++)
        #pragma unroll
        for (int j = 0; j < 8; j++)
            #pragma unroll
            for (int k = 0; k < 4; k++) acc[i][j][k] = 0.f;

    int wm = wid >> 1;
    int wn = wid & 1;

    // 2 tiles per K-chunk of 32: A, W. 3-stage ring: buffer = c % 3.
    auto issue = [&](int c) {
        int kc = c * 32;
        uint32_t stOff = (uint32_t)(c % 3) * 20480u;
        #pragma unroll
        for (int i = 0; i < 4; i++) {
            int idx = tid + i * 256;
            int tile = idx >> 9;
            int i2 = idx & 511;
            int r = i2 >> 2, j = i2 & 3;
            uint32_t dst = sbase + stOff + (uint32_t)tile * 10240u + (uint32_t)(r * SA + j * 8) * 2;
            const __half* src;
            if (tile == 0) src = g_Ah + (size_t)(rowBase + r) * NHn + kc + j * 8;
            else           src = Bw + (size_t)r * NHn + kc + j * 8;
            cp16(dst, src);
        }
        asm volatile("cp.async.commit_group;" ::: "memory");
    };

    auto compute = [&](int c) {
        uint32_t stOff = (uint32_t)(c % 3) * 20480u;
        uint32_t aB = sbase + stOff;
        uint32_t bB = aB + 10240u;
        #pragma unroll
        for (int ks = 0; ks < 2; ks++) {
            uint32_t av[2][4];
            #pragma unroll
            for (int mb = 0; mb < 2; mb++) {
                int row = wm * 32 + mb * 16 + (lane & 15);
                int col = ks * 16 + ((lane >> 4) << 3);
                ldsm4(av[mb], aB + (uint32_t)(row * SA + col) * 2);
            }
            #pragma unroll
            for (int ng = 0; ng < 4; ng++) {
                int n    = wn * 64 + ng * 16 + (lane & 7) + ((lane >> 4) << 3);
                int kcol = ks * 16 + ((lane >> 3) & 1) * 8;
                uint32_t b[4];
                ldsm4(b, bB + (uint32_t)(n * SA + kcol) * 2);
                #pragma unroll
                for (int mb = 0; mb < 2; mb++) {
                    mma16816(acc[mb][ng * 2 + 0], av[mb], b[0], b[1]);
                    mma16816(acc[mb][ng * 2 + 1], av[mb], b[2], b[3]);
                }
            }
        }
    };

    issue(0);
    issue(1);
    #pragma unroll
    for (int c = 0; c < 8; c++) {
        if (c < 7) asm volatile("cp.async.wait_group 1;" ::: "memory");
        else       asm volatile("cp.async.wait_group 0;" ::: "memory");
        __syncthreads();
        compute(c);
        if (c + 2 < 8) issue(c + 2);   // buffer (c+2)%3: disjoint from c%3 and (c+1)%3
    }

    // ---- epilogue: write fp16 z + fused el/er ---------------------------------
    int g = lane >> 2, tig = lane & 3;
    int headG = (nOff >> 6) + wn;
    #pragma unroll
    for (int mb = 0; mb < 2; mb++) {
        float pl0 = 0.f, pl1 = 0.f, pr0 = 0.f, pr1 = 0.f;
        #pragma unroll
        for (int nt = 0; nt < 8; nt++) {
            int row0 = rowBase + wm * 32 + mb * 16 + g;
            int row1 = row0 + 8;
            int colL = nt * 8 + tig * 2;
            int col  = nOff + wn * 64 + colL;
            if (row0 < Nn) {
                __half2 hv = __floats2half2_rn(acc[mb][nt][0], acc[mb][nt][1]);
                *(__half2*)((__half*)g_z + (size_t)row0 * (ETn * NHn) + t * NHn + col) = hv;
            }
            if (row1 < Nn) {
                __half2 hv = __floats2half2_rn(acc[mb][nt][2], acc[mb][nt][3]);
                *(__half2*)((__half*)g_z + (size_t)row1 * (ETn * NHn) + t * NHn + col) = hv;
            }
            float al0 = s_al[wn][colL], al1 = s_al[wn][colL + 1];
            float ar0 = s_ar[wn][colL], ar1 = s_ar[wn][colL + 1];
            pl0 = fmaf(acc[mb][nt][0], al0, fmaf(acc[mb][nt][1], al1, pl0));
            pl1 = fmaf(acc[mb][nt][2], al0, fmaf(acc[mb][nt][3], al1, pl1));
            pr0 = fmaf(acc[mb][nt][0], ar0, fmaf(acc[mb][nt][1], ar1, pr0));
            pr1 = fmaf(acc[mb][nt][2], ar0, fmaf(acc[mb][nt][3], ar1, pr1));
        }
        pl0 += __shfl_xor_sync(0xffffffffu, pl0, 1);
        pl0 += __shfl_xor_sync(0xffffffffu, pl0, 2);
        pl1 += __shfl_xor_sync(0xffffffffu, pl1, 1);
        pl1 += __shfl_xor_sync(0xffffffffu, pl1, 2);
        pr0 += __shfl_xor_sync(0xffffffffu, pr0, 1);
        pr0 += __shfl_xor_sync(0xffffffffu, pr0, 2);
        pr1 += __shfl_xor_sync(0xffffffffu, pr1, 1);
        pr1 += __shfl_xor_sync(0xffffffffu, pr1, 2);
        if (tig == 0) {
            int row0 = rowBase + wm * 32 + mb * 16 + g;
            int row1 = row0 + 8;
            if (row0 < Nn) {
                g_el[((size_t)t * Nn + row0) * Hn + headG] = pl0;
                g_er[((size_t)t * Nn + row0) * Hn + headG] = pr0;
            }
            if (row1 < Nn) {
                g_el[((size_t)t * Nn + row1) * Hn + headG] = pl1;
                g_er[((size_t)t * Nn + row1) * Hn + headG] = pr1;
            }
        }
    }
}

// ---------------- edge softmax + aggregation (ALL etypes, one launch) ----------
// outmode: 0 = write g_h fp32; 1 = relu + fp16 into g_Ah (next layer's GEMM A)
__global__ void aggregate_kernel(const float* __restrict__ bias, int l, int outmode) {
    int d = (blockIdx.x * blockDim.x + threadIdx.x) >> 5;
    if (d >= Nn) return;
    int lane = threadIdx.x & 31;
    int myh = lane >> 3;
    const unsigned F = 0xffffffffu;

    float a[8] = {0.f, 0.f, 0.f, 0.f, 0.f, 0.f, 0.f, 0.f};
    {
        const float* bl = bias + (size_t)l * ETn * NHn;
        #pragma unroll
        for (int tt = 0; tt < ETn; tt++) {
            float4 u0 = *(const float4*)(bl + tt * NHn + lane * 8);
            float4 u1 = *(const float4*)(bl + tt * NHn + lane * 8 + 4);
            a[0] += u0.x; a[1] += u0.y; a[2] += u0.z; a[3] += u0.w;
            a[4] += u1.x; a[5] += u1.y; a[6] += u1.z; a[7] += u1.w;
        }
    }

    #pragma unroll
    for (int t = 0; t < ETn; t++) {
        int s0  = g_off[t * (Nn + 1) + d];
        int deg = g_off[t * (Nn + 1) + d + 1] - s0;
        if (deg <= 0) continue;
        float4 er4 = *(const float4*)&g_er[((size_t)t * Nn + d) * Hn];
        const unsigned short* csr = g_csr_src + (size_t)t * Ee + s0;
        const __half* zbase = g_z + t * NHn;

        if (deg <= 32) {
            int s = 0;
            float e0 = -1e30f, e1 = -1e30f, e2 = -1e30f, e3 = -1e30f;
            if (lane < deg) {
                s = csr[lane];
                float4 e = *(const float4*)&g_el[((size_t)t * Nn + s) * Hn];
                e0 = lrelu(e.x + er4.x); e1 = lrelu(e.y + er4.y);
                e2 = lrelu(e.z + er4.z); e3 = lrelu(e.w + er4.w);
            }
            float m0 = e0, m1 = e1, m2 = e2, m3 = e3;
            #pragma unroll
            for (int o = 16; o; o >>= 1) {
                m0 = fmaxf(m0, __shfl_xor_sync(F, m0, o));
                m1 = fmaxf(m1, __shfl_xor_sync(F, m1, o));
                m2 = fmaxf(m2, __shfl_xor_sync(F, m2, o));
                m3 = fmaxf(m3, __shfl_xor_sync(F, m3, o));
            }
            float w0 = 0.f, w1 = 0.f, w2 = 0.f, w3 = 0.f;
            if (lane < deg) {
                w0 = expf(e0 - m0); w1 = expf(e1 - m1);
                w2 = expf(e2 - m2); w3 = expf(e3 - m3);
            }
            float q0 = w0, q1 = w1, q2 = w2, q3 = w3;
            #pragma unroll
            for (int o = 16; o; o >>= 1) {
                q0 += __shfl_xor_sync(F, q0, o);
                q1 += __shfl_xor_sync(F, q1, o);
                q2 += __shfl_xor_sync(F, q2, o);
                q3 += __shfl_xor_sync(F, q3, o);
            }
            w0 *= (1.f / q0); w1 *= (1.f / q1); w2 *= (1.f / q2); w3 *= (1.f / q3);

            __half2 h01 = __floats2half2_rn(w0, w1);
            __half2 h23 = __floats2half2_rn(w2, w3);
            uint32_t pa01 = *(uint32_t*)&h01, pa23 = *(uint32_t*)&h23;

            int j = 0;
            for (; j + 8 <= deg; j += 8) {
                int sj[8]; float alv[8]; uint4 qv[8];
                #pragma unroll
                for (int u = 0; u < 8; u++) {
                    sj[u] = __shfl_sync(F, s, j + u);
                    uint32_t q01 = __shfl_sync(F, pa01, j + u);
                    uint32_t q23 = __shfl_sync(F, pa23, j + u);
                    alv[u] = pick_alpha(q01, q23, myh);
                }
                #pragma unroll
                for (int u = 0; u < 8; u++)
                    qv[u] = *(const uint4*)(zbase + (size_t)sj[u] * (ETn * NHn) + lane * 8);
                #pragma unroll
                for (int u = 0; u < 8; u++) acc8(a, qv[u], alv[u]);
            }
            for (; j < deg; j++) {
                int sj = __shfl_sync(F, s, j);
                uint32_t q01 = __shfl_sync(F, pa01, j);
                uint32_t q23 = __shfl_sync(F, pa23, j);
                float alpha = pick_alpha(q01, q23, myh);
                uint4 qv = *(const uint4*)(zbase + (size_t)sj * (ETn * NHn) + lane * 8);
                acc8(a, qv, alpha);
            }
        } else {
            float m0 = -1e30f, m1 = -1e30f, m2 = -1e30f, m3 = -1e30f;
            for (int bse = 0; bse < deg; bse += 32) {
                int i = bse + lane;
                if (i < deg) {
                    int s = csr[i];
                    float4 e = *(const float4*)&g_el[((size_t)t * Nn + s) * Hn];
                    m0 = fmaxf(m0, lrelu(e.x + er4.x));
                    m1 = fmaxf(m1, lrelu(e.y + er4.y));
                    m2 = fmaxf(m2, lrelu(e.z + er4.z));
                    m3 = fmaxf(m3, lrelu(e.w + er4.w));
                }
            }
            #pragma unroll
            for (int o = 16; o; o >>= 1) {
                m0 = fmaxf(m0, __shfl_xor_sync(F, m0, o));
                m1 = fmaxf(m1, __shfl_xor_sync(F, m1, o));
                m2 = fmaxf(m2, __shfl_xor_sync(F, m2, o));
                m3 = fmaxf(m3, __shfl_xor_sync(F, m3, o));
            }
            float q0 = 0.f, q1 = 0.f, q2 = 0.f, q3 = 0.f;
            for (int bse = 0; bse < deg; bse += 32) {
                int i = bse + lane;
                if (i < deg) {
                    int s = csr[i];
                    float4 e = *(const float4*)&g_el[((size_t)t * Nn + s) * Hn];
                    q0 += expf(lrelu(e.x + er4.x) - m0);
                    q1 += expf(lrelu(e.y + er4.y) - m1);
                    q2 += expf(lrelu(e.z + er4.z) - m2);
                    q3 += expf(lrelu(e.w + er4.w) - m3);
                }
            }
            #pragma unroll
            for (int o = 16; o; o >>= 1) {
                q0 += __shfl_xor_sync(F, q0, o);
                q1 += __shfl_xor_sync(F, q1, o);
                q2 += __shfl_xor_sync(F, q2, o);
                q3 += __shfl_xor_sync(F, q3, o);
            }
            float i0 = 1.f / q0, i1 = 1.f / q1, i2 = 1.f / q2, i3 = 1.f / q3;

            for (int bse = 0; bse < deg; bse += 32) {
                int i = bse + lane;
                int s = 0;
                float w0 = 0.f, w1 = 0.f, w2 = 0.f, w3 = 0.f;
                if (i < deg) {
                    s = csr[i];
                    float4 e = *(const float4*)&g_el[((size_t)t * Nn + s) * Hn];
                    w0 = expf(lrelu(e.x + er4.x) - m0) * i0;
                    w1 = expf(lrelu(e.y + er4.y) - m1) * i1;
                    w2 = expf(lrelu(e.z + er4.z) - m2) * i2;
                    w3 = expf(lrelu(e.w + er4.w) - m3) * i3;
                }
                __half2 h01 = __floats2half2_rn(w0, w1);
                __half2 h23 = __floats2half2_rn(w2, w3);
                uint32_t pa01 = *(uint32_t*)&h01, pa23 = *(uint32_t*)&h23;

                int cnt = min(32, deg - bse);
                int j = 0;
                for (; j + 4 <= cnt; j += 4) {
                    int sj[4]; float alv[4]; uint4 qv[4];
                    #pragma unroll
                    for (int u = 0; u < 4; u++) {
                        sj[u] = __shfl_sync(F, s, j + u);
                        uint32_t q01 = __shfl_sync(F, pa01, j + u);
                        uint32_t q23 = __shfl_sync(F, pa23, j + u);
                        alv[u] = pick_alpha(q01, q23, myh);
                    }
                    #pragma unroll
                    for (int u = 0; u < 4; u++)
                        qv[u] = *(const uint4*)(zbase + (size_t)sj[u] * (ETn * NHn) + lane * 8);
                    #pragma unroll
                    for (int u = 0; u < 4; u++) acc8(a, qv[u], alv[u]);
                }
                for (; j < cnt; j++) {
                    int sj = __shfl_sync(F, s, j);
                    uint32_t q01 = __shfl_sync(F, pa01, j);
                    uint32_t q23 = __shfl_sync(F, pa23, j);
                    float alpha = pick_alpha(q01, q23, myh);
                    uint4 qv = *(const uint4*)(zbase + (size_t)sj * (ETn * NHn) + lane * 8);
                    acc8(a, qv, alpha);
                }
            }
        }
    }

    if (outmode == 0) {
        float* hrow = g_h + (size_t)d * NHn + lane * 8;
        __stcs((float4*)(hrow),     make_float4(a[0], a[1], a[2], a[3]));
        __stcs((float4*)(hrow + 4), make_float4(a[4], a[5], a[6], a[7]));
    } else {
        __half2 p0 = __floats2half2_rn(fmaxf(a[0], 0.f), fmaxf(a[1], 0.f));
        __half2 p1 = __floats2half2_rn(fmaxf(a[2], 0.f), fmaxf(a[3], 0.f));
        __half2 p2 = __floats2half2_rn(fmaxf(a[4], 0.f), fmaxf(a[5], 0.f));
        __half2 p3 = __floats2half2_rn(fmaxf(a[6], 0.f), fmaxf(a[7], 0.f));
        __stcs((uint4*)((uint16_t*)g_Ah + (size_t)d * NHn + lane * 8),
               make_uint4(*(uint32_t*)&p0, *(uint32_t*)&p1, *(uint32_t*)&p2, *(uint32_t*)&p3));
    }
}

// ---------------- final linear --------------------------------------------------
__global__ void linear_kernel(const float* __restrict__ lw, const float* __restrict__ lb,
                              float* __restrict__ out) {
    __shared__ float sw[NHn * NCn];
    int tid = threadIdx.x;
    for (int i = tid; i < NHn * NCn; i += 256) sw[i] = lw[i];
    __syncthreads();
    int n = blockIdx.x * 16 + (tid >> 4);
    int c = tid & 15;
    if (n >= Nn) return;
    float s = lb[c];
    const float* hr = g_h + (size_t)n * NHn;
    #pragma unroll 4
    for (int k = 0; k < NHn; k += 4) {
        float4 hv = __ldcs((const float4*)(hr + k));
        s = fmaf(hv.x, sw[(k + 0) * NCn + c], s);
        s = fmaf(hv.y, sw[(k + 1) * NCn + c], s);
        s = fmaf(hv.z, sw[(k + 2) * NCn + c], s);
        s = fmaf(hv.w, sw[(k + 3) * NCn + c], s);
    }
    out[(size_t)n * NCn + c] = s;
}

// ---------------- launch --------------------------------------------------------
extern "C" void kernel_launch(void* const* d_in, const int* in_sizes, int n_in,
                              void* d_out, int out_size) {
    const float* x    = (const float*)d_in[0];
    const int*   src  = (const int*)d_in[1];
    const int*   dst  = (const int*)d_in[2];
    const float* W    = (const float*)d_in[3];
    const float* al   = (const float*)d_in[4];
    const float* ar   = (const float*)d_in[5];
    const float* bias = (const float*)d_in[6];
    const float* lw   = (const float*)d_in[7];
    const float* lb   = (const float*)d_in[8];
    float* out = (float*)d_out;

    const int GEMM_SMEM = 61440;   // 3 stages x 2 tiles x 10240 B
    cudaFuncSetAttribute(gemm_hmma_kernel, cudaFuncAttributeMaxDynamicSharedMemorySize, GEMM_SMEM);

    void* p_deg = nullptr;
    void* p_cur = nullptr;
    cudaGetSymbolAddress(&p_deg, g_deg);
    cudaGetSymbolAddress(&p_cur, g_cur);
    cudaMemsetAsync(p_deg, 0, sizeof(int) * ETn * Nn);
    cudaMemsetAsync(p_cur, 0, sizeof(int) * ETn * Nn);

    int hpN = (NW + NAq) > (ETn * Ee) ? (NW + NAq) : (ETn * Ee);
    hist_prep_kernel<<<(hpN + 255) / 256, 256>>>(dst, W, x);
    scan_kernel<<<ETn, 1024>>>();
    scatter_kernel<<<(ETn * Ee + 255) / 256, 256>>>(src, dst);

    for (int l = 0; l < Ln; l++) {
        dim3 gg((Nn + 127) / 128, ETn * 2);
        gemm_hmma_kernel<<<gg, 256, GEMM_SMEM>>>(l, al, ar);
        int outmode = (l != Ln - 1) ? 1 : 0;
        aggregate_kernel<<<(Nn * 32 + 255) / 256, 256>>>(bias, l, outmode);
    }
    linear_kernel<<<(Nn + 15) / 16, 256>>>(lw, lb, out);
}

// round 16
// speedup vs baseline: 1.5090x; 1.5090x over previous
#include <cuda_runtime.h>
#include <cuda_fp16.h>
#include <math.h>
#include <stdint.h>

#define Nn    50000
#define NnPad 50176
#define Ee    800000
#define ETn   3
#define Ln    3
#define Hn    4
#define DHn   64
#define NHn   256
#define NCn   16
#define SA    40          // smem row stride in halves (32 data + 8 pad)

// ---------------- scratch (device globals) -----------------------------------
__device__ __align__(16) float g_h[Nn * NHn];
__device__ __align__(16) __half g_z[Nn * ETn * NHn];   // z in fp16 (77 MB, L2-resident)
__device__ __align__(16) float g_el[ETn * Nn * Hn];
__device__ __align__(16) float g_er[ETn * Nn * Hn];
__device__ int g_deg[ETn * Nn];
__device__ int g_cur[ETn * Nn];
__device__ int g_off[ETn * (Nn + 1)];
__device__ __align__(16) unsigned short g_csr_src[ETn * Ee];   // u16 node ids (< 65536)

// single fp16 A and W operands
__device__ __align__(16) __half g_Ah[NnPad * NHn];
__device__ __align__(16) __half g_WT[Ln * ETn * NHn * NHn];   // [l][t][n][k]

// ---------------- helpers ------------------------------------------------------
__device__ __forceinline__ float lrelu(float v) { return v > 0.f ? v : 0.2f * v; }

__device__ __forceinline__ uint32_t smem_u32(const void* p) {
    uint32_t a;
    asm("{ .reg .u64 t; cvta.to.shared.u64 t, %1; cvt.u32.u64 %0, t; }" : "=r"(a) : "l"(p));
    return a;
}
__device__ __forceinline__ void cp16(uint32_t dst, const void* src) {
    asm volatile("cp.async.cg.shared.global [%0], [%1], 16;" :: "r"(dst), "l"(src) : "memory");
}
__device__ __forceinline__ void ldsm4(uint32_t* r, uint32_t addr) {
    asm volatile("ldmatrix.sync.aligned.m8n8.x4.shared.b16 {%0,%1,%2,%3}, [%4];"
                 : "=r"(r[0]), "=r"(r[1]), "=r"(r[2]), "=r"(r[3]) : "r"(addr));
}
__device__ __forceinline__ void mma16816(float* c, const uint32_t* a, uint32_t b0, uint32_t b1) {
    asm volatile(
        "mma.sync.aligned.m16n8k16.row.col.f32.f16.f16.f32 "
        "{%0,%1,%2,%3}, {%4,%5,%6,%7}, {%8,%9}, {%0,%1,%2,%3};"
        : "+f"(c[0]), "+f"(c[1]), "+f"(c[2]), "+f"(c[3])
        : "r"(a[0]), "r"(a[1]), "r"(a[2]), "r"(a[3]), "r"(b0), "r"(b1));
}
// accumulate 8 fp16 z values (one uint4) scaled by alpha
__device__ __forceinline__ void acc8(float* a, uint4 q, float alpha) {
    __half2 h0 = *(__half2*)&q.x, h1 = *(__half2*)&q.y;
    __half2 h2 = *(__half2*)&q.z, h3 = *(__half2*)&q.w;
    float2 f0 = __half22float2(h0), f1 = __half22float2(h1);
    float2 f2 = __half22float2(h2), f3 = __half22float2(h3);
    a[0] = fmaf(alpha, f0.x, a[0]); a[1] = fmaf(alpha, f0.y, a[1]);
    a[2] = fmaf(alpha, f1.x, a[2]); a[3] = fmaf(alpha, f1.y, a[3]);
    a[4] = fmaf(alpha, f2.x, a[4]); a[5] = fmaf(alpha, f2.y, a[5]);
    a[6] = fmaf(alpha, f3.x, a[6]); a[7] = fmaf(alpha, f3.y, a[7]);
}
// extract this lane's head alpha from two packed half2 (3-shfl broadcast scheme)
__device__ __forceinline__ float pick_alpha(uint32_t q01, uint32_t q23, int myh) {
    uint32_t qq = (myh & 2) ? q23 : q01;
    __half2 hh = *(__half2*)&qq;
    return (myh & 1) ? __high2float(hh) : __low2float(hh);
}

// ---------------- CSR hist + prep (independent work, one launch) ---------------
#define NW (Ln * ETn * NHn * NHn)
#define NAq (Nn * (NHn / 4))
__global__ void hist_prep_kernel(const int* __restrict__ dst,
                                 const float* __restrict__ W,
                                 const float* __restrict__ X) {
    int i = blockIdx.x * blockDim.x + threadIdx.x;
    if (i < ETn * Ee) {
        int t = i / Ee;
        atomicAdd(&g_deg[t * Nn + dst[i]], 1);
    }
    if (i < NW) {
        int lt = i / (NHn * NHn);
        int rem = i - lt * NHn * NHn;
        int k = rem / NHn;
        int n = rem - k * NHn;
        size_t o = (size_t)lt * NHn * NHn + (size_t)n * NHn + k;
        g_WT[o] = __float2half(W[i]);
    } else if (i < NW + NAq) {
        int i2 = i - NW;
        float4 v = *(const float4*)(X + (size_t)i2 * 4);
        __half2 a = __floats2half2_rn(v.x, v.y);
        __half2 b = __floats2half2_rn(v.z, v.w);
        *(uint2*)((uint16_t*)g_Ah + (size_t)i2 * 4) =
            make_uint2(*(uint32_t*)&a, *(uint32_t*)&b);
    }
}
__global__ void scan_kernel() {
    int t = blockIdx.x;
    int tid = threadIdx.x;
    __shared__ int warpsums[32];
    __shared__ int s_carry;
    if (tid == 0) s_carry = 0;
    __syncthreads();
    for (int base = 0; base < Nn; base += 1024) {
        int i = base + tid;
        int v = (i < Nn) ? g_deg[t * Nn + i] : 0;
        int x = v;
        #pragma unroll
        for (int o = 1; o < 32; o <<= 1) {
            int y = __shfl_up_sync(0xffffffffu, x, o);
            if ((tid & 31) >= o) x += y;
        }
        if ((tid & 31) == 31) warpsums[tid >> 5] = x;
        __syncthreads();
        if (tid < 32) {
            int w = warpsums[tid];
            #pragma unroll
            for (int o = 1; o < 32; o <<= 1) {
                int y = __shfl_up_sync(0xffffffffu, w, o);
                if (tid >= o) w += y;
            }
            warpsums[tid] = w;
        }
        __syncthreads();
        int add = (tid >= 32) ? warpsums[(tid >> 5) - 1] : 0;
        int incl = x + add;
        int c = s_carry;
        if (i < Nn) g_off[t * (Nn + 1) + i] = c + incl - v;
        __syncthreads();
        if (tid == 1023) s_carry = c + incl;
        __syncthreads();
    }
    if (tid == 0) g_off[t * (Nn + 1) + Nn] = s_carry;
}
__global__ void scatter_kernel(const int* __restrict__ src, const int* __restrict__ dst) {
    int i = blockIdx.x * blockDim.x + threadIdx.x;
    if (i >= ETn * Ee) return;
    int t = i / Ee;
    int d = dst[i];
    int p = atomicAdd(&g_cur[t * Nn + d], 1);
    g_csr_src[t * Ee + g_off[t * (Nn + 1) + d] + p] = (unsigned short)src[i];
}

// ---------------- HMMA GEMM (single fp16 A, corrected 3-stage pipeline) --------
__global__ __launch_bounds__(256, 2) void gemm_hmma_kernel(
        int l, const float* __restrict__ AL, const float* __restrict__ AR) {
    extern __shared__ char dyn[];
    __shared__ float s_al[2][DHn];
    __shared__ float s_ar[2][DHn];

    int tid  = threadIdx.x;
    int wid  = tid >> 5;
    int lane = tid & 31;
    int rowBase = blockIdx.x * 128;
    int t    = blockIdx.y >> 1;
    int nOff = (blockIdx.y & 1) * 128;

    const __half* Bw = g_WT + ((size_t)l * ETn + t) * NHn * NHn + (size_t)nOff * NHn;

    uint32_t sbase = smem_u32(dyn);

    if (tid < 128) {
        int w = tid >> 6, i = tid & 63;
        int hg = (nOff >> 6) + w;
        s_al[w][i] = AL[(((size_t)l * ETn + t) * Hn + hg) * DHn + i];
        s_ar[w][i] = AR[(((size_t)l * ETn + t) * Hn + hg) * DHn + i];
    }

    float acc[2][8][4];
    #pragma unroll
    for (int i = 0; i < 2; i++)
        #pragma unroll
        for (int j = 0; j < 8; j++)
            #pragma unroll
            for (int k = 0; k < 4; k++) acc[i][j][k] = 0.f;

    int wm = wid >> 1;
    int wn = wid & 1;

    // 2 tiles per K-chunk of 32: A, W. 3-stage ring: buffer = c % 3.
    auto issue = [&](int c) {
        int kc = c * 32;
        uint32_t stOff = (uint32_t)(c % 3) * 20480u;
        #pragma unroll
        for (int i = 0; i < 4; i++) {
            int idx = tid + i * 256;
            int tile = idx >> 9;
            int i2 = idx & 511;
            int r = i2 >> 2, j = i2 & 3;
            uint32_t dst = sbase + stOff + (uint32_t)tile * 10240u + (uint32_t)(r * SA + j * 8) * 2;
            const __half* src;
            if (tile == 0) src = g_Ah + (size_t)(rowBase + r) * NHn + kc + j * 8;
            else           src = Bw + (size_t)r * NHn + kc + j * 8;
            cp16(dst, src);
        }
        asm volatile("cp.async.commit_group;" ::: "memory");
    };

    auto compute = [&](int c) {
        uint32_t stOff = (uint32_t)(c % 3) * 20480u;
        uint32_t aB = sbase + stOff;
        uint32_t bB = aB + 10240u;
        #pragma unroll
        for (int ks = 0; ks < 2; ks++) {
            uint32_t av[2][4];
            #pragma unroll
            for (int mb = 0; mb < 2; mb++) {
                int row = wm * 32 + mb * 16 + (lane & 15);
                int col = ks * 16 + ((lane >> 4) << 3);
                ldsm4(av[mb], aB + (uint32_t)(row * SA + col) * 2);
            }
            #pragma unroll
            for (int ng = 0; ng < 4; ng++) {
                int n    = wn * 64 + ng * 16 + (lane & 7) + ((lane >> 4) << 3);
                int kcol = ks * 16 + ((lane >> 3) & 1) * 8;
                uint32_t b[4];
                ldsm4(b, bB + (uint32_t)(n * SA + kcol) * 2);
                #pragma unroll
                for (int mb = 0; mb < 2; mb++) {
                    mma16816(acc[mb][ng * 2 + 0], av[mb], b[0], b[1]);
                    mma16816(acc[mb][ng * 2 + 1], av[mb], b[2], b[3]);
                }
            }
        }
    };

    // issue-before-wait (R14 timing), 3 buffers -> no trailing barrier needed:
    // iteration c+1's issue(c+2) writes buffer (c+2)%3, disjoint from c%3
    // (straggler readers of compute(c)) and (c+1)%3 (in-flight group).
    issue(0);
    #pragma unroll
    for (int c = 0; c < 8; c++) {
        if (c + 1 < 8) {
            issue(c + 1);
            asm volatile("cp.async.wait_group 1;" ::: "memory");
        } else {
            asm volatile("cp.async.wait_group 0;" ::: "memory");
        }
        __syncthreads();
        compute(c);
    }

    // ---- epilogue: write fp16 z + fused el/er ---------------------------------
    int g = lane >> 2, tig = lane & 3;
    int headG = (nOff >> 6) + wn;
    #pragma unroll
    for (int mb = 0; mb < 2; mb++) {
        float pl0 = 0.f, pl1 = 0.f, pr0 = 0.f, pr1 = 0.f;
        #pragma unroll
        for (int nt = 0; nt < 8; nt++) {
            int row0 = rowBase + wm * 32 + mb * 16 + g;
            int row1 = row0 + 8;
            int colL = nt * 8 + tig * 2;
            int col  = nOff + wn * 64 + colL;
            if (row0 < Nn) {
                __half2 hv = __floats2half2_rn(acc[mb][nt][0], acc[mb][nt][1]);
                *(__half2*)((__half*)g_z + (size_t)row0 * (ETn * NHn) + t * NHn + col) = hv;
            }
            if (row1 < Nn) {
                __half2 hv = __floats2half2_rn(acc[mb][nt][2], acc[mb][nt][3]);
                *(__half2*)((__half*)g_z + (size_t)row1 * (ETn * NHn) + t * NHn + col) = hv;
            }
            float al0 = s_al[wn][colL], al1 = s_al[wn][colL + 1];
            float ar0 = s_ar[wn][colL], ar1 = s_ar[wn][colL + 1];
            pl0 = fmaf(acc[mb][nt][0], al0, fmaf(acc[mb][nt][1], al1, pl0));
            pl1 = fmaf(acc[mb][nt][2], al0, fmaf(acc[mb][nt][3], al1, pl1));
            pr0 = fmaf(acc[mb][nt][0], ar0, fmaf(acc[mb][nt][1], ar1, pr0));
            pr1 = fmaf(acc[mb][nt][2], ar0, fmaf(acc[mb][nt][3], ar1, pr1));
        }
        pl0 += __shfl_xor_sync(0xffffffffu, pl0, 1);
        pl0 += __shfl_xor_sync(0xffffffffu, pl0, 2);
        pl1 += __shfl_xor_sync(0xffffffffu, pl1, 1);
        pl1 += __shfl_xor_sync(0xffffffffu, pl1, 2);
        pr0 += __shfl_xor_sync(0xffffffffu, pr0, 1);
        pr0 += __shfl_xor_sync(0xffffffffu, pr0, 2);
        pr1 += __shfl_xor_sync(0xffffffffu, pr1, 1);
        pr1 += __shfl_xor_sync(0xffffffffu, pr1, 2);
        if (tig == 0) {
            int row0 = rowBase + wm * 32 + mb * 16 + g;
            int row1 = row0 + 8;
            if (row0 < Nn) {
                g_el[((size_t)t * Nn + row0) * Hn + headG] = pl0;
                g_er[((size_t)t * Nn + row0) * Hn + headG] = pr0;
            }
            if (row1 < Nn) {
                g_el[((size_t)t * Nn + row1) * Hn + headG] = pl1;
                g_er[((size_t)t * Nn + row1) * Hn + headG] = pr1;
            }
        }
    }
}

// ---------------- edge softmax + aggregation (ALL etypes, one launch) ----------
// outmode: 0 = write g_h fp32; 1 = relu + fp16 into g_Ah (next layer's GEMM A)
__global__ void aggregate_kernel(const float* __restrict__ bias, int l, int outmode) {
    int d = (blockIdx.x * blockDim.x + threadIdx.x) >> 5;
    if (d >= Nn) return;
    int lane = threadIdx.x & 31;
    int myh = lane >> 3;
    const unsigned F = 0xffffffffu;

    float a[8] = {0.f, 0.f, 0.f, 0.f, 0.f, 0.f, 0.f, 0.f};
    {
        const float* bl = bias + (size_t)l * ETn * NHn;
        #pragma unroll
        for (int tt = 0; tt < ETn; tt++) {
            float4 u0 = *(const float4*)(bl + tt * NHn + lane * 8);
            float4 u1 = *(const float4*)(bl + tt * NHn + lane * 8 + 4);
            a[0] += u0.x; a[1] += u0.y; a[2] += u0.z; a[3] += u0.w;
            a[4] += u1.x; a[5] += u1.y; a[6] += u1.z; a[7] += u1.w;
        }
    }

    #pragma unroll
    for (int t = 0; t < ETn; t++) {
        int s0  = g_off[t * (Nn + 1) + d];
        int deg = g_off[t * (Nn + 1) + d + 1] - s0;
        if (deg <= 0) continue;
        float4 er4 = *(const float4*)&g_er[((size_t)t * Nn + d) * Hn];
        const unsigned short* csr = g_csr_src + (size_t)t * Ee + s0;
        const __half* zbase = g_z + t * NHn;

        if (deg <= 32) {
            int s = 0;
            float e0 = -1e30f, e1 = -1e30f, e2 = -1e30f, e3 = -1e30f;
            if (lane < deg) {
                s = csr[lane];
                float4 e = *(const float4*)&g_el[((size_t)t * Nn + s) * Hn];
                e0 = lrelu(e.x + er4.x); e1 = lrelu(e.y + er4.y);
                e2 = lrelu(e.z + er4.z); e3 = lrelu(e.w + er4.w);
            }
            float m0 = e0, m1 = e1, m2 = e2, m3 = e3;
            #pragma unroll
            for (int o = 16; o; o >>= 1) {
                m0 = fmaxf(m0, __shfl_xor_sync(F, m0, o));
                m1 = fmaxf(m1, __shfl_xor_sync(F, m1, o));
                m2 = fmaxf(m2, __shfl_xor_sync(F, m2, o));
                m3 = fmaxf(m3, __shfl_xor_sync(F, m3, o));
            }
            float w0 = 0.f, w1 = 0.f, w2 = 0.f, w3 = 0.f;
            if (lane < deg) {
                w0 = expf(e0 - m0); w1 = expf(e1 - m1);
                w2 = expf(e2 - m2); w3 = expf(e3 - m3);
            }
            float q0 = w0, q1 = w1, q2 = w2, q3 = w3;
            #pragma unroll
            for (int o = 16; o; o >>= 1) {
                q0 += __shfl_xor_sync(F, q0, o);
                q1 += __shfl_xor_sync(F, q1, o);
                q2 += __shfl_xor_sync(F, q2, o);
                q3 += __shfl_xor_sync(F, q3, o);
            }
            w0 *= (1.f / q0); w1 *= (1.f / q1); w2 *= (1.f / q2); w3 *= (1.f / q3);

            __half2 h01 = __floats2half2_rn(w0, w1);
            __half2 h23 = __floats2half2_rn(w2, w3);
            uint32_t pa01 = *(uint32_t*)&h01, pa23 = *(uint32_t*)&h23;

            int j = 0;
            for (; j + 8 <= deg; j += 8) {
                int sj[8]; float alv[8]; uint4 qv[8];
                #pragma unroll
                for (int u = 0; u < 8; u++) {
                    sj[u] = __shfl_sync(F, s, j + u);
                    uint32_t q01 = __shfl_sync(F, pa01, j + u);
                    uint32_t q23 = __shfl_sync(F, pa23, j + u);
                    alv[u] = pick_alpha(q01, q23, myh);
                }
                #pragma unroll
                for (int u = 0; u < 8; u++)
                    qv[u] = *(const uint4*)(zbase + (size_t)sj[u] * (ETn * NHn) + lane * 8);
                #pragma unroll
                for (int u = 0; u < 8; u++) acc8(a, qv[u], alv[u]);
            }
            for (; j < deg; j++) {
                int sj = __shfl_sync(F, s, j);
                uint32_t q01 = __shfl_sync(F, pa01, j);
                uint32_t q23 = __shfl_sync(F, pa23, j);
                float alpha = pick_alpha(q01, q23, myh);
                uint4 qv = *(const uint4*)(zbase + (size_t)sj * (ETn * NHn) + lane * 8);
                acc8(a, qv, alpha);
            }
        } else {
            float m0 = -1e30f, m1 = -1e30f, m2 = -1e30f, m3 = -1e30f;
            for (int bse = 0; bse < deg; bse += 32) {
                int i = bse + lane;
                if (i < deg) {
                    int s = csr[i];
                    float4 e = *(const float4*)&g_el[((size_t)t * Nn + s) * Hn];
                    m0 = fmaxf(m0, lrelu(e.x + er4.x));
                    m1 = fmaxf(m1, lrelu(e.y + er4.y));
                    m2 = fmaxf(m2, lrelu(e.z + er4.z));
                    m3 = fmaxf(m3, lrelu(e.w + er4.w));
                }
            }
            #pragma unroll
            for (int o = 16; o; o >>= 1) {
                m0 = fmaxf(m0, __shfl_xor_sync(F, m0, o));
                m1 = fmaxf(m1, __shfl_xor_sync(F, m1, o));
                m2 = fmaxf(m2, __shfl_xor_sync(F, m2, o));
                m3 = fmaxf(m3, __shfl_xor_sync(F, m3, o));
            }
            float q0 = 0.f, q1 = 0.f, q2 = 0.f, q3 = 0.f;
            for (int bse = 0; bse < deg; bse += 32) {
                int i = bse + lane;
                if (i < deg) {
                    int s = csr[i];
                    float4 e = *(const float4*)&g_el[((size_t)t * Nn + s) * Hn];
                    q0 += expf(lrelu(e.x + er4.x) - m0);
                    q1 += expf(lrelu(e.y + er4.y) - m1);
                    q2 += expf(lrelu(e.z + er4.z) - m2);
                    q3 += expf(lrelu(e.w + er4.w) - m3);
                }
            }
            #pragma unroll
            for (int o = 16; o; o >>= 1) {
                q0 += __shfl_xor_sync(F, q0, o);
                q1 += __shfl_xor_sync(F, q1, o);
                q2 += __shfl_xor_sync(F, q2, o);
                q3 += __shfl_xor_sync(F, q3, o);
            }
            float i0 = 1.f / q0, i1 = 1.f / q1, i2 = 1.f / q2, i3 = 1.f / q3;

            for (int bse = 0; bse < deg; bse += 32) {
                int i = bse + lane;
                int s = 0;
                float w0 = 0.f, w1 = 0.f, w2 = 0.f, w3 = 0.f;
                if (i < deg) {
                    s = csr[i];
                    float4 e = *(const float4*)&g_el[((size_t)t * Nn + s) * Hn];
                    w0 = expf(lrelu(e.x + er4.x) - m0) * i0;
                    w1 = expf(lrelu(e.y + er4.y) - m1) * i1;
                    w2 = expf(lrelu(e.z + er4.z) - m2) * i2;
                    w3 = expf(lrelu(e.w + er4.w) - m3) * i3;
                }
                __half2 h01 = __floats2half2_rn(w0, w1);
                __half2 h23 = __floats2half2_rn(w2, w3);
                uint32_t pa01 = *(uint32_t*)&h01, pa23 = *(uint32_t*)&h23;

                int cnt = min(32, deg - bse);
                int j = 0;
                for (; j + 4 <= cnt; j += 4) {
                    int sj[4]; float alv[4]; uint4 qv[4];
                    #pragma unroll
                    for (int u = 0; u < 4; u++) {
                        sj[u] = __shfl_sync(F, s, j + u);
                        uint32_t q01 = __shfl_sync(F, pa01, j + u);
                        uint32_t q23 = __shfl_sync(F, pa23, j + u);
                        alv[u] = pick_alpha(q01, q23, myh);
                    }
                    #pragma unroll
                    for (int u = 0; u < 4; u++)
                        qv[u] = *(const uint4*)(zbase + (size_t)sj[u] * (ETn * NHn) + lane * 8);
                    #pragma unroll
                    for (int u = 0; u < 4; u++) acc8(a, qv[u], alv[u]);
                }
                for (; j < cnt; j++) {
                    int sj = __shfl_sync(F, s, j);
                    uint32_t q01 = __shfl_sync(F, pa01, j);
                    uint32_t q23 = __shfl_sync(F, pa23, j);
                    float alpha = pick_alpha(q01, q23, myh);
                    uint4 qv = *(const uint4*)(zbase + (size_t)sj * (ETn * NHn) + lane * 8);
                    acc8(a, qv, alpha);
                }
            }
        }
    }

    if (outmode == 0) {
        float* hrow = g_h + (size_t)d * NHn + lane * 8;
        __stcs((float4*)(hrow),     make_float4(a[0], a[1], a[2], a[3]));
        __stcs((float4*)(hrow + 4), make_float4(a[4], a[5], a[6], a[7]));
    } else {
        __half2 p0 = __floats2half2_rn(fmaxf(a[0], 0.f), fmaxf(a[1], 0.f));
        __half2 p1 = __floats2half2_rn(fmaxf(a[2], 0.f), fmaxf(a[3], 0.f));
        __half2 p2 = __floats2half2_rn(fmaxf(a[4], 0.f), fmaxf(a[5], 0.f));
        __half2 p3 = __floats2half2_rn(fmaxf(a[6], 0.f), fmaxf(a[7], 0.f));
        __stcs((uint4*)((uint16_t*)g_Ah + (size_t)d * NHn + lane * 8),
               make_uint4(*(uint32_t*)&p0, *(uint32_t*)&p1, *(uint32_t*)&p2, *(uint32_t*)&p3));
    }
}

// ---------------- final linear --------------------------------------------------
__global__ void linear_kernel(const float* __restrict__ lw, const float* __restrict__ lb,
                              float* __restrict__ out) {
    __shared__ float sw[NHn * NCn];
    int tid = threadIdx.x;
    for (int i = tid; i < NHn * NCn; i += 256) sw[i] = lw[i];
    __syncthreads();
    int n = blockIdx.x * 16 + (tid >> 4);
    int c = tid & 15;
    if (n >= Nn) return;
    float s = lb[c];
    const float* hr = g_h + (size_t)n * NHn;
    #pragma unroll 4
    for (int k = 0; k < NHn; k += 4) {
        float4 hv = __ldcs((const float4*)(hr + k));
        s = fmaf(hv.x, sw[(k + 0) * NCn + c], s);
        s = fmaf(hv.y, sw[(k + 1) * NCn + c], s);
        s = fmaf(hv.z, sw[(k + 2) * NCn + c], s);
        s = fmaf(hv.w, sw[(k + 3) * NCn + c], s);
    }
    out[(size_t)n * NCn + c] = s;
}

// ---------------- launch --------------------------------------------------------
extern "C" void kernel_launch(void* const* d_in, const int* in_sizes, int n_in,
                              void* d_out, int out_size) {
    const float* x    = (const float*)d_in[0];
    const int*   src  = (const int*)d_in[1];
    const int*   dst  = (const int*)d_in[2];
    const float* W    = (const float*)d_in[3];
    const float* al   = (const float*)d_in[4];
    const float* ar   = (const float*)d_in[5];
    const float* bias = (const float*)d_in[6];
    const float* lw   = (const float*)d_in[7];
    const float* lb   = (const float*)d_in[8];
    float* out = (float*)d_out;

    const int GEMM_SMEM = 61440;   // 3 stages x 2 tiles x 10240 B
    cudaFuncSetAttribute(gemm_hmma_kernel, cudaFuncAttributeMaxDynamicSharedMemorySize, GEMM_SMEM);

    void* p_deg = nullptr;
    void* p_cur = nullptr;
    cudaGetSymbolAddress(&p_deg, g_deg);
    cudaGetSymbolAddress(&p_cur, g_cur);
    cudaMemsetAsync(p_deg, 0, sizeof(int) * ETn * Nn);
    cudaMemsetAsync(p_cur, 0, sizeof(int) * ETn * Nn);

    int hpN = (NW + NAq) > (ETn * Ee) ? (NW + NAq) : (ETn * Ee);
    hist_prep_kernel<<<(hpN + 255) / 256, 256>>>(dst, W, x);
    scan_kernel<<<ETn, 1024>>>();
    scatter_kernel<<<(ETn * Ee + 255) / 256, 256>>>(src, dst);

    for (int l = 0; l < Ln; l++) {
        dim3 gg((Nn + 127) / 128, ETn * 2);
        gemm_hmma_kernel<<<gg, 256, GEMM_SMEM>>>(l, al, ar);
        int outmode = (l != Ln - 1) ? 1 : 0;
        aggregate_kernel<<<(Nn * 32 + 255) / 256, 256>>>(bias, l, outmode);
    }
    linear_kernel<<<(Nn + 15) / 16, 256>>>(lw, lb, out);
}